// round 15
// baseline (speedup 1.0000x reference)
#include <cuda_runtime.h>
#include <math.h>

// Problem constants
#define CC    128
#define HW    4096
#define NPIX  8192
#define NCLS  4
#define KSEL  50
#define KPAD  56                       // layout rows; only 50 used after exact trim
#define MAXCAND 1024
#define SCALE 20.6099291555566197f     // log2(e)/0.07
#define NTHR  512
#define SELBLK 32                      // k_select grid (4 selection + all gather)

#define RS 132                         // padded row stride (floats) for X/P tiles
#define CS (KPAD * CC + 4)             // class stride (floats): 7172

// smem layout (float offsets) for k_fused
#define OFF_X    0
#define OFF_P    8448
#define OFF_G    16896
#define OFF_RED  45584                 // 3*8*64
#define OFF_EX   47120                 // 16*64
#define OFF_INV  48144
#define OFF_INVP 48208
#define OFF_NOM  48272
#define OFF_CLS  48336
#define OFF_PERM 48400
#define OFF_SLOT 48464
#define OFF_CNT  48528
#define SMEM_FLOATS 48544
#define SMEM_BYTES  (SMEM_FLOATS * 4)  // 194176

typedef unsigned long long u64;

__device__ __forceinline__ void fma2(u64& acc, u64 a, u64 b) {
    asm("fma.rn.f32x2 %0, %1, %2, %0;" : "+l"(acc) : "l"(a), "l"(b));
}
__device__ __forceinline__ float2 upk(u64 v) {
    float2 r; asm("mov.b64 {%0,%1}, %2;" : "=f"(r.x), "=f"(r.y) : "l"(v)); return r;
}

// ---------------- device scratch ----------------
__device__ float g_Gs[NCLS][KPAD][CC];  // selected negatives, normalized AND pre-scaled by SCALE
__device__ int   g_sel[NCLS][KSEL];     // selected pixel indices per class
__device__ float g_acc;                 // reset by last ticket each launch
__device__ unsigned int g_tick;
__device__ unsigned int g_selflag;      // classes whose selection is published (0..4)
__device__ unsigned int g_gtick;        // gather-completion ticket (resets flags)

// ================= kernel 1: selection (blocks 0-3, atomic-free bisection) + distributed gather =================
__global__ __launch_bounds__(1024, 1) void k_select(const float* __restrict__ neg,
                                                    const float* __restrict__ nl) {
    __shared__ int   sW[7][32];          // per-warp partial counts for 7 probes
    __shared__ int   sTot[8];            // reduced counts
    __shared__ float cv[MAXCAND];
    __shared__ int   ci[MAXCAND];
    __shared__ int   ssel[KSEL];
    __shared__ int   s_cnt;

    int blk  = blockIdx.x;
    int t    = threadIdx.x;
    int lane = t & 31, wid = t >> 5;

    // ---------- selection: blocks 0..3 only ----------
    if (blk < NCLS) {
        int s = blk;

        // seg/prob for 8 pixels per thread, straight from negative_logits
        bool     val[8];
        unsigned pb[8];                  // prob bit pattern (order-isomorphic for positive floats)
        float    pvv[8];
        #pragma unroll
        for (int j = 0; j < 8; j++) {
            int i = t + j * 1024;
            int b = i >> 12, rem = i & 4095;
            const float* pn = nl + (size_t)b * NCLS * HW + rem;
            float l0 = pn[0], l1 = pn[HW], l2 = pn[2 * HW], l3 = pn[3 * HW];
            int amax = 0; float m = l0;
            if (l1 > m) { m = l1; amax = 1; }
            if (l2 > m) { m = l2; amax = 2; }
            if (l3 > m) { m = l3; amax = 3; }
            float sum = __expf(l0 - m) + __expf(l1 - m) + __expf(l2 - m) + __expf(l3 - m);
            float p = 1.0f / sum;
            val[j] = (amax != s);
            pvv[j] = p;
            pb[j]  = __float_as_uint(p);
        }
        if (t == 0) s_cnt = 0;

        // ---- 8-way bisection for the 50th-largest threshold (no atomics) ----
        unsigned lo = 0x3E800000u;       // bits(0.25): all valid probs >= 0.25
        unsigned hi = 0x3F800000u;       // bits(1.0)
        for (int round = 0; round < 9; round++) {
            unsigned width = hi - lo;
            unsigned mids[7];
            #pragma unroll
            for (int q = 0; q < 7; q++) mids[q] = lo + ((u64)width * (q + 1) >> 3);

            int c[7];
            #pragma unroll
            for (int q = 0; q < 7; q++) c[q] = 0;
            #pragma unroll
            for (int j = 0; j < 8; j++) {
                if (val[j]) {
                    unsigned v = pb[j];
                    #pragma unroll
                    for (int q = 0; q < 7; q++) c[q] += (v >= mids[q]);
                }
            }
            #pragma unroll
            for (int q = 0; q < 7; q++) {
                #pragma unroll
                for (int off = 16; off; off >>= 1)
                    c[q] += __shfl_xor_sync(0xffffffffu, c[q], off);
                if (lane == 0) sW[q][wid] = c[q];
            }
            __syncthreads();
            if (t < 7) {
                int sum = 0;
                #pragma unroll
                for (int w2 = 0; w2 < 32; w2++) sum += sW[t][w2];
                sTot[t] = sum;
            }
            __syncthreads();
            // pick largest probe with count >= KSEL (probe0 = lo has cnt >= 50 by invariant)
            unsigned nlo = lo, nhi = mids[0];
            #pragma unroll
            for (int q = 0; q < 7; q++) {
                if (sTot[q] >= KSEL) { nlo = mids[q]; nhi = (q < 6) ? mids[q + 1] : hi; }
            }
            lo = nlo; hi = nhi;
            __syncthreads();
        }
        unsigned thr = lo;               // cnt(>= thr) >= 50, tie window tiny

        // ---- collect candidates (few; cheap atomics) ----
        #pragma unroll
        for (int j = 0; j < 8; j++) {
            if (val[j] && pb[j] >= thr) {
                int pos = atomicAdd(&s_cnt, 1);
                if (pos < MAXCAND) { cv[pos] = pvv[j]; ci[pos] = t + j * 1024; }
            }
        }
        __syncthreads();
        int M = min(s_cnt, MAXCAND);

        // exact rank (value desc, index asc tie-break == lax.top_k)
        for (int c2 = t; c2 < M; c2 += 1024) {
            float v = cv[c2]; int id = ci[c2];
            int r = 0;
            for (int m = 0; m < M; m++) {
                float vm = cv[m];
                if (vm > v || (vm == v && ci[m] < id)) r++;
            }
            if (r < KSEL) ssel[r] = id;
        }
        __syncthreads();

        // publish indices, then raise flag
        if (t < KSEL) g_sel[s][t] = ssel[t];
        __syncthreads();
        if (t == 0) {
            __threadfence();
            atomicAdd(&g_selflag, 1u);
        }
    }

    // ---------- all 32 blocks: wait for all 4 classes published ----------
    if (t == 0) {
        while (atomicAdd(&g_selflag, 0u) < NCLS) __nanosleep(64);
    }
    __syncthreads();

    // ---------- distributed gather: one (class,k) row per warp ----------
    {
        int T = blk + SELBLK * wid;               // task id 0..199 spread across blocks
        if (T < NCLS * KSEL) {
            int cls = T / KSEL, k = T - cls * KSEL;
            int n = g_sel[cls][k];
            int b = n >> 12, rem = n & 4095;
            const float* p = neg + (size_t)b * CC * HW + rem;
            float v[4];
            #pragma unroll
            for (int j = 0; j < 4; j++)
                v[j] = p[(size_t)(lane + j * 32) * HW];
            float ss = v[0]*v[0] + v[1]*v[1] + v[2]*v[2] + v[3]*v[3];
            #pragma unroll
            for (int off = 16; off; off >>= 1)
                ss += __shfl_xor_sync(0xffffffffu, ss, off);
            float inv = SCALE / fmaxf(sqrtf(ss), 1e-12f);
            #pragma unroll
            for (int j = 0; j < 4; j++)
                g_Gs[cls][k][lane + j * 32] = v[j] * inv;
        }
    }

    // ---------- reset flags for next graph replay ----------
    __syncthreads();
    if (t == 0) {
        __threadfence();
        unsigned int old = atomicAdd(&g_gtick, 1u);
        if (old == SELBLK - 1) {
            g_selflag = 0u;
            g_gtick   = 0u;
        }
    }
}

// ================= kernel 2: fused norm + class-sorted block GEMM (R12/R14 verbatim) =================
__global__ __launch_bounds__(NTHR, 1) void k_fused(const float* __restrict__ inp,
                                                   const float* __restrict__ pos,
                                                   const float* __restrict__ il,
                                                   float* __restrict__ out) {
    extern __shared__ float sm[];
    float* sX    = sm + OFF_X;
    float* sP    = sm + OFF_P;
    float* sG    = sm + OFF_G;
    float* sRed  = sm + OFF_RED;
    float* sEx   = sm + OFF_EX;
    float* sInv  = sm + OFF_INV;
    float* sInvP = sm + OFF_INVP;
    float* sNom  = sm + OFF_NOM;
    int*   sCls  = (int*)(sm + OFF_CLS);
    int*   sPerm = (int*)(sm + OFF_PERM);
    int*   sSlot = (int*)(sm + OFF_SLOT);
    int*   sCnt  = (int*)(sm + OFF_CNT);

    int tid = threadIdx.x;
    int n   = tid & 63;
    int cg  = tid >> 6;                  // 0..7 channel group
    int px0 = blockIdx.x * 64;
    int b   = px0 >> 12, rem = px0 & 4095;

    if (tid < 8) sCnt[tid] = 0;

    // ---- G prefetch via cp.async: overlaps phase A ----
    {
        const float4* gsrc = (const float4*)g_Gs;     // 4*56*128/4 = 7168 float4
        #pragma unroll
        for (int it = 0; it < 14; it++) {
            int f4 = tid + it * NTHR;
            int cls = f4 / 1792;
            int r4  = f4 - cls * 1792;
            unsigned dst = (unsigned)__cvta_generic_to_shared(&sG[cls * CS + r4 * 4]);
            asm volatile("cp.async.cg.shared.global [%0], [%1], 16;\n"
                         :: "r"(dst), "l"(gsrc + f4));
        }
        asm volatile("cp.async.commit_group;\n");
    }

    // ---- Phase A: load x/p to registers, partial norms; tid<64: class from input_logits ----
    float xv[16], pv[16];
    {
        const float* bx = inp + (size_t)b * CC * HW + rem + n;
        const float* bp = pos + (size_t)b * CC * HW + rem + n;
        float sx2 = 0.f, sp2 = 0.f, sxp = 0.f;
        #pragma unroll
        for (int j = 0; j < 16; j++) {
            int c = cg * 16 + j;
            xv[j] = bx[(size_t)c * HW];
            pv[j] = bp[(size_t)c * HW];
            sx2 += xv[j] * xv[j];
            sp2 += pv[j] * pv[j];
            sxp += xv[j] * pv[j];
        }
        sRed[(0 * 8 + cg) * 64 + n] = sx2;
        sRed[(1 * 8 + cg) * 64 + n] = sp2;
        sRed[(2 * 8 + cg) * 64 + n] = sxp;
    }
    if (tid < 64) {
        const float* pi = il + (size_t)b * NCLS * HW + rem + tid;
        float l0 = pi[0], l1 = pi[HW], l2 = pi[2 * HW], l3 = pi[3 * HW];
        int amax = 0; float m = l0;
        if (l1 > m) { m = l1; amax = 1; }
        if (l2 > m) { m = l2; amax = 2; }
        if (l3 > m) { m = l3; amax = 3; }
        sCls[tid] = amax;
    }
    __syncthreads();

    if (tid < 64) {
        float a0 = 0.f, a1 = 0.f, a2 = 0.f;
        #pragma unroll
        for (int g = 0; g < 8; g++) {
            a0 += sRed[(0 * 8 + g) * 64 + tid];
            a1 += sRed[(1 * 8 + g) * 64 + tid];
            a2 += sRed[(2 * 8 + g) * 64 + tid];
        }
        float invi = 1.0f / fmaxf(sqrtf(a0), 1e-12f);
        float invp = 1.0f / fmaxf(sqrtf(a1), 1e-12f);
        sInv[tid]  = invi;
        sInvP[tid] = invp;
        sNom[tid]  = exp2f(a2 * invi * invp * SCALE);
        atomicAdd(&sCnt[sCls[tid]], 1);
    }
    __syncthreads();
    if (tid == 0) {
        int acc = 0;
        #pragma unroll
        for (int c = 0; c < 4; c++) { sCnt[4 + c] = acc; acc += sCnt[c]; }
    }
    __syncthreads();
    if (tid < 64) {
        int pos2 = atomicAdd(&sCnt[4 + sCls[tid]], 1);
        sPerm[pos2] = tid;
        sSlot[tid]  = pos2;
    }
    __syncthreads();

    // store normalized x̂/p̂ at class-sorted rows
    {
        float invi = sInv[n], invp = sInvP[n];
        int slot = sSlot[n];
        float* dx = sX + slot * RS + cg * 16;
        float* dp = sP + slot * RS + cg * 16;
        #pragma unroll
        for (int j4 = 0; j4 < 4; j4++) {
            *(float4*)&dx[j4 * 4] = make_float4(xv[j4*4]*invi, xv[j4*4+1]*invi,
                                                xv[j4*4+2]*invi, xv[j4*4+3]*invi);
            *(float4*)&dp[j4 * 4] = make_float4(pv[j4*4]*invp, pv[j4*4+1]*invp,
                                                pv[j4*4+2]*invp, pv[j4*4+3]*invp);
        }
    }

    // G must have landed; make all smem writes visible
    asm volatile("cp.async.wait_group 0;\n" ::: "memory");
    __syncthreads();

    // ---- Phase C: register-tiled GEMM, exact k=50 (kg 0..6: 7 k; kg 7: k=49 only) ----
    {
        int lane = tid & 31, w = tid >> 5;           // 16 warps
        int half = w & 1, kg = w >> 1;               // kg 0..7
        int slot = half * 32 + lane;
        int cls  = sCls[sPerm[slot]];
        const float* gx = sX + slot * RS;
        const float* gp = sP + slot * RS;
        const float* gg = sG + cls * CS + (kg * 7) * CC;

        float eN, eA;
        if (kg < 7) {
            u64 aN[7], aA[7];
            #pragma unroll
            for (int kk = 0; kk < 7; kk++) { aN[kk] = 0ull; aA[kk] = 0ull; }

            #pragma unroll 4
            for (int c4 = 0; c4 < 32; c4++) {
                ulonglong2 x2 = *(const ulonglong2*)&gx[c4 * 4];
                ulonglong2 p2 = *(const ulonglong2*)&gp[c4 * 4];
                #pragma unroll
                for (int kk = 0; kk < 7; kk++) {
                    ulonglong2 g2 = *(const ulonglong2*)&gg[kk * CC + c4 * 4];
                    fma2(aN[kk], x2.x, g2.x); fma2(aN[kk], x2.y, g2.y);
                    fma2(aA[kk], p2.x, g2.x); fma2(aA[kk], p2.y, g2.y);
                }
            }
            eN = 0.f; eA = 0.f;
            #pragma unroll
            for (int kk = 0; kk < 7; kk++) {           // k = kg*7+kk <= 48 < KSEL: no guard
                float2 tn = upk(aN[kk]);
                float2 ta = upk(aA[kk]);
                eN += exp2f(tn.x + tn.y);
                eA += exp2f(ta.x + ta.y);
            }
        } else {
            // kg == 7: single row k = 49
            u64 aN0 = 0ull, aA0 = 0ull;
            #pragma unroll 8
            for (int c4 = 0; c4 < 32; c4++) {
                ulonglong2 x2 = *(const ulonglong2*)&gx[c4 * 4];
                ulonglong2 p2 = *(const ulonglong2*)&gp[c4 * 4];
                ulonglong2 g2 = *(const ulonglong2*)&gg[c4 * 4];
                fma2(aN0, x2.x, g2.x); fma2(aN0, x2.y, g2.y);
                fma2(aA0, p2.x, g2.x); fma2(aA0, p2.y, g2.y);
            }
            float2 tn = upk(aN0), ta = upk(aA0);
            eN = exp2f(tn.x + tn.y);
            eA = exp2f(ta.x + ta.y);
        }
        sEx[kg * 64 + slot]       = eN;
        sEx[(8 + kg) * 64 + slot] = eA;
    }
    __syncthreads();

    // ---- epilogue + ticketed output ----
    if (tid < 64) {
        float accN = 0.f, accA = 0.f;
        #pragma unroll
        for (int g = 0; g < 8; g++) {
            accN += sEx[g * 64 + tid];
            accA += sEx[(8 + g) * 64 + tid];
        }
        float nom = sNom[sPerm[tid]];
        float term = logf(nom / (accN + nom + 1e-8f))
                   + logf(nom / (accA + nom + 1e-8f));
        #pragma unroll
        for (int off = 16; off; off >>= 1)
            term += __shfl_xor_sync(0xffffffffu, term, off);
        if ((tid & 31) == 0) atomicAdd(&g_acc, term);
    }
    __syncthreads();

    if (tid == 0) {
        __threadfence();
        unsigned int ticket = atomicAdd(&g_tick, 1u);
        if (ticket == gridDim.x - 1) {
            float v = atomicAdd(&g_acc, 0.0f);
            out[0] = -v / (float)NPIX;
            g_tick = 0u;
            g_acc  = 0.0f;              // reset for next graph replay
        }
    }
}

// ---------------- launch ----------------
extern "C" void kernel_launch(void* const* d_in, const int* in_sizes, int n_in,
                              void* d_out, int out_size) {
    const float* inp = (const float*)d_in[0];   // input    [2,128,64,64]
    const float* pos = (const float*)d_in[1];   // positive
    const float* neg = (const float*)d_in[2];   // negative
    const float* il  = (const float*)d_in[3];   // input_logits    [2,4,64,64]
    const float* nl  = (const float*)d_in[4];   // negative_logits
    float* out = (float*)d_out;

    cudaFuncSetAttribute(k_fused, cudaFuncAttributeMaxDynamicSharedMemorySize, SMEM_BYTES);

    k_select<<<SELBLK, 1024>>>(neg, nl);
    k_fused<<<NPIX / 64, NTHR, SMEM_BYTES>>>(inp, pos, il, out);
}

// round 16
// speedup vs baseline: 1.5203x; 1.5203x over previous
#include <cuda_runtime.h>
#include <math.h>

// Problem constants
#define CC    128
#define HW    4096
#define NPIX  8192
#define NCLS  4
#define KSEL  50
#define KPAD  56                       // layout rows; only 50 used after exact trim
#define NBIN  1024
#define MAXCAND 2048
#define SCALE 20.6099291555566197f     // log2(e)/0.07
#define NTHR  512
#define SELBLK 32                      // k_select grid (4 selection + all gather)
#define FILT  478                      // prob >= ~0.60 prefilter bin (verified fallback below)

#define RS 132                         // padded row stride (floats) for X/P tiles
#define CS (KPAD * CC + 4)             // class stride (floats): 7172

// smem layout (float offsets) for k_fused
#define OFF_X    0
#define OFF_P    8448
#define OFF_G    16896
#define OFF_RED  45584                 // 3*8*64
#define OFF_EX   47120                 // 16*64
#define OFF_INV  48144
#define OFF_INVP 48208
#define OFF_NOM  48272
#define OFF_CLS  48336
#define OFF_PERM 48400
#define OFF_SLOT 48464
#define OFF_CNT  48528
#define SMEM_FLOATS 48544
#define SMEM_BYTES  (SMEM_FLOATS * 4)  // 194176

typedef unsigned long long u64;

__device__ __forceinline__ void fma2(u64& acc, u64 a, u64 b) {
    asm("fma.rn.f32x2 %0, %1, %2, %0;" : "+l"(acc) : "l"(a), "l"(b));
}
__device__ __forceinline__ float2 upk(u64 v) {
    float2 r; asm("mov.b64 {%0,%1}, %2;" : "=f"(r.x), "=f"(r.y) : "l"(v)); return r;
}

// ---------------- device scratch ----------------
__device__ float g_Gs[NCLS][KPAD][CC];  // selected negatives, normalized AND pre-scaled by SCALE
__device__ int   g_sel[NCLS][KSEL];     // selected pixel indices per class
__device__ float g_acc;                 // reset by last ticket each launch
__device__ unsigned int g_tick;
__device__ unsigned int g_selflag;      // classes whose selection is published (0..4)
__device__ unsigned int g_gtick;        // gather-completion ticket (resets flags)

// ================= kernel 1: selection (blocks 0-3) + distributed gather (all 32) =================
__global__ __launch_bounds__(1024, 1) void k_select(const float* __restrict__ neg,
                                                    const float* __restrict__ nl) {
    __shared__ int   hist[NBIN];
    __shared__ int   schunk[32];
    __shared__ float cv[MAXCAND];
    __shared__ int   ci[MAXCAND];
    __shared__ int   ssel[KSEL];
    __shared__ int   sflag[3];           // [0]=cnt [1]=binThr [2]=total

    int blk = blockIdx.x;
    int t   = threadIdx.x;

    // ---------- selection: blocks 0..3 only ----------
    if (blk < NCLS) {
        int s = blk;

        // seg/prob for 8 pixels per thread, straight from negative_logits
        int  seg[8];
        float pv[8];
        int  bin[8];
        #pragma unroll
        for (int j = 0; j < 8; j++) {
            int i = t + j * 1024;
            int b = i >> 12, rem = i & 4095;
            const float* pn = nl + (size_t)b * NCLS * HW + rem;
            float l0 = pn[0], l1 = pn[HW], l2 = pn[2 * HW], l3 = pn[3 * HW];
            int amax = 0; float m = l0;
            if (l1 > m) { m = l1; amax = 1; }
            if (l2 > m) { m = l2; amax = 2; }
            if (l3 > m) { m = l3; amax = 3; }
            float sum = __expf(l0 - m) + __expf(l1 - m) + __expf(l2 - m) + __expf(l3 - m);
            seg[j] = amax;
            pv[j]  = 1.0f / sum;
            int bb = (int)((pv[j] - 0.25f) * (1024.0f / 0.75f));
            bin[j] = max(0, min(NBIN - 1, bb));
        }

        // histogram with prefilter; verified total, unfiltered fallback if < KSEL
        int filt = FILT;
        int binThr = 0;
        for (int attempt = 0; attempt < 2; attempt++) {
            for (int i = t; i < NBIN; i += 1024) hist[i] = 0;
            __syncthreads();
            #pragma unroll
            for (int j = 0; j < 8; j++)
                if (seg[j] != s && bin[j] >= filt) atomicAdd(&hist[bin[j]], 1);
            __syncthreads();
            if (t < 32) {
                int sum = 0;
                #pragma unroll
                for (int j = 0; j < 32; j++) sum += hist[t * 32 + j];
                schunk[t] = sum;
            }
            __syncthreads();
            if (t == 0) {
                int total = 0;
                #pragma unroll
                for (int cb = 0; cb < 32; cb++) total += schunk[cb];
                int thr = filt;
                if (total >= KSEL) {
                    int cum = 0;
                    for (int cb = 31; cb >= 0; cb--) {
                        if (cum + schunk[cb] >= KSEL) {
                            for (int bb = cb * 32 + 31; bb >= cb * 32; bb--) {
                                cum += hist[bb];
                                if (cum >= KSEL) { thr = bb; break; }
                            }
                            break;
                        }
                        cum += schunk[cb];
                    }
                }
                sflag[1] = thr;
                sflag[2] = total;
                sflag[0] = 0;
            }
            __syncthreads();
            binThr = sflag[1];
            if (sflag[2] >= KSEL) break;
            filt = 0;                    // fallback: unfiltered (never taken in practice)
            __syncthreads();
        }

        // collect candidates (everything in bin >= binThr; superset of top-50)
        #pragma unroll
        for (int j = 0; j < 8; j++) {
            if (seg[j] != s && bin[j] >= binThr) {
                int pos = atomicAdd(&sflag[0], 1);
                if (pos < MAXCAND) { cv[pos] = pv[j]; ci[pos] = t + j * 1024; }
            }
        }
        __syncthreads();
        int M = min(sflag[0], MAXCAND);

        // exact rank (value desc, index asc tie-break == lax.top_k)
        for (int c = t; c < M; c += 1024) {
            float v = cv[c]; int id = ci[c];
            int r = 0;
            for (int m = 0; m < M; m++) {
                float vm = cv[m];
                if (vm > v || (vm == v && ci[m] < id)) r++;
            }
            if (r < KSEL) ssel[r] = id;
        }
        __syncthreads();

        // publish indices, then raise flag
        if (t < KSEL) g_sel[s][t] = ssel[t];
        __syncthreads();
        if (t == 0) {
            __threadfence();
            atomicAdd(&g_selflag, 1u);
        }
    }

    // ---------- all 32 blocks: wait for all 4 classes published ----------
    if (t == 0) {
        while (atomicAdd(&g_selflag, 0u) < NCLS) __nanosleep(64);
    }
    __syncthreads();

    // ---------- distributed gather: one (class,k) row per warp ----------
    {
        int w = t >> 5, lane = t & 31;
        int T = blk + SELBLK * w;                 // task id 0..199 spread across blocks
        if (T < NCLS * KSEL) {
            int cls = T / KSEL, k = T - cls * KSEL;
            int n = g_sel[cls][k];
            int b = n >> 12, rem = n & 4095;
            const float* p = neg + (size_t)b * CC * HW + rem;
            float v[4];
            #pragma unroll
            for (int j = 0; j < 4; j++)
                v[j] = p[(size_t)(lane + j * 32) * HW];
            float ss = v[0]*v[0] + v[1]*v[1] + v[2]*v[2] + v[3]*v[3];
            #pragma unroll
            for (int off = 16; off; off >>= 1)
                ss += __shfl_xor_sync(0xffffffffu, ss, off);
            float inv = SCALE / fmaxf(sqrtf(ss), 1e-12f);
            #pragma unroll
            for (int j = 0; j < 4; j++)
                g_Gs[cls][k][lane + j * 32] = v[j] * inv;
        }
    }

    // ---------- reset flags for next graph replay ----------
    __syncthreads();
    if (t == 0) {
        __threadfence();
        unsigned int old = atomicAdd(&g_gtick, 1u);
        if (old == SELBLK - 1) {
            g_selflag = 0u;
            g_gtick   = 0u;
        }
    }
}

// ================= kernel 2: fused norm + class-sorted block GEMM (R14 verbatim) =================
__global__ __launch_bounds__(NTHR, 1) void k_fused(const float* __restrict__ inp,
                                                   const float* __restrict__ pos,
                                                   const float* __restrict__ il,
                                                   float* __restrict__ out) {
    extern __shared__ float sm[];
    float* sX    = sm + OFF_X;
    float* sP    = sm + OFF_P;
    float* sG    = sm + OFF_G;
    float* sRed  = sm + OFF_RED;
    float* sEx   = sm + OFF_EX;
    float* sInv  = sm + OFF_INV;
    float* sInvP = sm + OFF_INVP;
    float* sNom  = sm + OFF_NOM;
    int*   sCls  = (int*)(sm + OFF_CLS);
    int*   sPerm = (int*)(sm + OFF_PERM);
    int*   sSlot = (int*)(sm + OFF_SLOT);
    int*   sCnt  = (int*)(sm + OFF_CNT);

    int tid = threadIdx.x;
    int n   = tid & 63;
    int cg  = tid >> 6;                  // 0..7 channel group
    int px0 = blockIdx.x * 64;
    int b   = px0 >> 12, rem = px0 & 4095;

    if (tid < 8) sCnt[tid] = 0;

    // ---- G prefetch via cp.async: overlaps phase A ----
    {
        const float4* gsrc = (const float4*)g_Gs;     // 4*56*128/4 = 7168 float4
        #pragma unroll
        for (int it = 0; it < 14; it++) {
            int f4 = tid + it * NTHR;
            int cls = f4 / 1792;
            int r4  = f4 - cls * 1792;
            unsigned dst = (unsigned)__cvta_generic_to_shared(&sG[cls * CS + r4 * 4]);
            asm volatile("cp.async.cg.shared.global [%0], [%1], 16;\n"
                         :: "r"(dst), "l"(gsrc + f4));
        }
        asm volatile("cp.async.commit_group;\n");
    }

    // ---- Phase A: load x/p to registers, partial norms; tid<64: class from input_logits ----
    float xv[16], pv[16];
    {
        const float* bx = inp + (size_t)b * CC * HW + rem + n;
        const float* bp = pos + (size_t)b * CC * HW + rem + n;
        float sx2 = 0.f, sp2 = 0.f, sxp = 0.f;
        #pragma unroll
        for (int j = 0; j < 16; j++) {
            int c = cg * 16 + j;
            xv[j] = bx[(size_t)c * HW];
            pv[j] = bp[(size_t)c * HW];
            sx2 += xv[j] * xv[j];
            sp2 += pv[j] * pv[j];
            sxp += xv[j] * pv[j];
        }
        sRed[(0 * 8 + cg) * 64 + n] = sx2;
        sRed[(1 * 8 + cg) * 64 + n] = sp2;
        sRed[(2 * 8 + cg) * 64 + n] = sxp;
    }
    if (tid < 64) {
        const float* pi = il + (size_t)b * NCLS * HW + rem + tid;
        float l0 = pi[0], l1 = pi[HW], l2 = pi[2 * HW], l3 = pi[3 * HW];
        int amax = 0; float m = l0;
        if (l1 > m) { m = l1; amax = 1; }
        if (l2 > m) { m = l2; amax = 2; }
        if (l3 > m) { m = l3; amax = 3; }
        sCls[tid] = amax;
    }
    __syncthreads();

    if (tid < 64) {
        float a0 = 0.f, a1 = 0.f, a2 = 0.f;
        #pragma unroll
        for (int g = 0; g < 8; g++) {
            a0 += sRed[(0 * 8 + g) * 64 + tid];
            a1 += sRed[(1 * 8 + g) * 64 + tid];
            a2 += sRed[(2 * 8 + g) * 64 + tid];
        }
        float invi = 1.0f / fmaxf(sqrtf(a0), 1e-12f);
        float invp = 1.0f / fmaxf(sqrtf(a1), 1e-12f);
        sInv[tid]  = invi;
        sInvP[tid] = invp;
        sNom[tid]  = exp2f(a2 * invi * invp * SCALE);
        atomicAdd(&sCnt[sCls[tid]], 1);
    }
    __syncthreads();
    if (tid == 0) {
        int acc = 0;
        #pragma unroll
        for (int c = 0; c < 4; c++) { sCnt[4 + c] = acc; acc += sCnt[c]; }
    }
    __syncthreads();
    if (tid < 64) {
        int pos2 = atomicAdd(&sCnt[4 + sCls[tid]], 1);
        sPerm[pos2] = tid;
        sSlot[tid]  = pos2;
    }
    __syncthreads();

    // store normalized x̂/p̂ at class-sorted rows
    {
        float invi = sInv[n], invp = sInvP[n];
        int slot = sSlot[n];
        float* dx = sX + slot * RS + cg * 16;
        float* dp = sP + slot * RS + cg * 16;
        #pragma unroll
        for (int j4 = 0; j4 < 4; j4++) {
            *(float4*)&dx[j4 * 4] = make_float4(xv[j4*4]*invi, xv[j4*4+1]*invi,
                                                xv[j4*4+2]*invi, xv[j4*4+3]*invi);
            *(float4*)&dp[j4 * 4] = make_float4(pv[j4*4]*invp, pv[j4*4+1]*invp,
                                                pv[j4*4+2]*invp, pv[j4*4+3]*invp);
        }
    }

    // G must have landed; make all smem writes visible
    asm volatile("cp.async.wait_group 0;\n" ::: "memory");
    __syncthreads();

    // ---- Phase C: register-tiled GEMM, exact k=50 (kg 0..6: 7 k; kg 7: k=49 only) ----
    {
        int lane = tid & 31, w = tid >> 5;           // 16 warps
        int half = w & 1, kg = w >> 1;               // kg 0..7
        int slot = half * 32 + lane;
        int cls  = sCls[sPerm[slot]];
        const float* gx = sX + slot * RS;
        const float* gp = sP + slot * RS;
        const float* gg = sG + cls * CS + (kg * 7) * CC;

        float eN, eA;
        if (kg < 7) {
            u64 aN[7], aA[7];
            #pragma unroll
            for (int kk = 0; kk < 7; kk++) { aN[kk] = 0ull; aA[kk] = 0ull; }

            #pragma unroll 4
            for (int c4 = 0; c4 < 32; c4++) {
                ulonglong2 x2 = *(const ulonglong2*)&gx[c4 * 4];
                ulonglong2 p2 = *(const ulonglong2*)&gp[c4 * 4];
                #pragma unroll
                for (int kk = 0; kk < 7; kk++) {
                    ulonglong2 g2 = *(const ulonglong2*)&gg[kk * CC + c4 * 4];
                    fma2(aN[kk], x2.x, g2.x); fma2(aN[kk], x2.y, g2.y);
                    fma2(aA[kk], p2.x, g2.x); fma2(aA[kk], p2.y, g2.y);
                }
            }
            eN = 0.f; eA = 0.f;
            #pragma unroll
            for (int kk = 0; kk < 7; kk++) {           // k = kg*7+kk <= 48 < KSEL: no guard
                float2 tn = upk(aN[kk]);
                float2 ta = upk(aA[kk]);
                eN += exp2f(tn.x + tn.y);
                eA += exp2f(ta.x + ta.y);
            }
        } else {
            // kg == 7: single row k = 49
            u64 aN0 = 0ull, aA0 = 0ull;
            #pragma unroll 8
            for (int c4 = 0; c4 < 32; c4++) {
                ulonglong2 x2 = *(const ulonglong2*)&gx[c4 * 4];
                ulonglong2 p2 = *(const ulonglong2*)&gp[c4 * 4];
                ulonglong2 g2 = *(const ulonglong2*)&gg[c4 * 4];
                fma2(aN0, x2.x, g2.x); fma2(aN0, x2.y, g2.y);
                fma2(aA0, p2.x, g2.x); fma2(aA0, p2.y, g2.y);
            }
            float2 tn = upk(aN0), ta = upk(aA0);
            eN = exp2f(tn.x + tn.y);
            eA = exp2f(ta.x + ta.y);
        }
        sEx[kg * 64 + slot]       = eN;
        sEx[(8 + kg) * 64 + slot] = eA;
    }
    __syncthreads();

    // ---- epilogue + ticketed output ----
    if (tid < 64) {
        float accN = 0.f, accA = 0.f;
        #pragma unroll
        for (int g = 0; g < 8; g++) {
            accN += sEx[g * 64 + tid];
            accA += sEx[(8 + g) * 64 + tid];
        }
        float nom = sNom[sPerm[tid]];
        float term = logf(nom / (accN + nom + 1e-8f))
                   + logf(nom / (accA + nom + 1e-8f));
        #pragma unroll
        for (int off = 16; off; off >>= 1)
            term += __shfl_xor_sync(0xffffffffu, term, off);
        if ((tid & 31) == 0) atomicAdd(&g_acc, term);
    }
    __syncthreads();

    if (tid == 0) {
        __threadfence();
        unsigned int ticket = atomicAdd(&g_tick, 1u);
        if (ticket == gridDim.x - 1) {
            float v = atomicAdd(&g_acc, 0.0f);
            out[0] = -v / (float)NPIX;
            g_tick = 0u;
            g_acc  = 0.0f;              // reset for next graph replay
        }
    }
}

// ---------------- launch ----------------
extern "C" void kernel_launch(void* const* d_in, const int* in_sizes, int n_in,
                              void* d_out, int out_size) {
    const float* inp = (const float*)d_in[0];   // input    [2,128,64,64]
    const float* pos = (const float*)d_in[1];   // positive
    const float* neg = (const float*)d_in[2];   // negative
    const float* il  = (const float*)d_in[3];   // input_logits    [2,4,64,64]
    const float* nl  = (const float*)d_in[4];   // negative_logits
    float* out = (float*)d_out;

    cudaFuncSetAttribute(k_fused, cudaFuncAttributeMaxDynamicSharedMemorySize, SMEM_BYTES);

    k_select<<<SELBLK, 1024>>>(neg, nl);
    k_fused<<<NPIX / 64, NTHR, SMEM_BYTES>>>(inp, pos, il, out);
}

// round 17
// speedup vs baseline: 1.6422x; 1.0801x over previous
#include <cuda_runtime.h>
#include <math.h>

// Problem constants
#define CC    128
#define HW    4096
#define NPIX  8192
#define NCLS  4
#define KSEL  50
#define KPAD  56                       // layout rows; only 50 used
#define NBIN  1024
#define MAXCAND 2048
#define SCALE 20.6099291555566197f     // log2(e)/0.07
#define NTHR  512
#define SELBLK 32                      // k_select grid (4 selection + all gather)

#define RS 132                         // padded row stride (floats) for X/P tiles
#define CS (KPAD * CC + 4)             // class stride (floats): 7172

// smem layout (float offsets) for k_fused
#define OFF_X    0
#define OFF_P    8448
#define OFF_G    16896
#define OFF_RED  45584                 // 3*8*64
#define OFF_EX   47120                 // 16*64 region (10*64 used)
#define OFF_INV  48144
#define OFF_INVP 48208
#define OFF_NOM  48272
#define OFF_CLS  48336
#define OFF_PERM 48400
#define OFF_SLOT 48464
#define OFF_CNT  48528
#define SMEM_FLOATS 48544
#define SMEM_BYTES  (SMEM_FLOATS * 4)  // 194176

typedef unsigned long long u64;

__device__ __forceinline__ void fma2(u64& acc, u64 a, u64 b) {
    asm("fma.rn.f32x2 %0, %1, %2, %0;" : "+l"(acc) : "l"(a), "l"(b));
}
__device__ __forceinline__ float2 upk(u64 v) {
    float2 r; asm("mov.b64 {%0,%1}, %2;" : "=f"(r.x), "=f"(r.y) : "l"(v)); return r;
}

// ---------------- device scratch ----------------
__device__ float g_Gs[NCLS][KPAD][CC];  // selected negatives, normalized AND pre-scaled by SCALE
__device__ int   g_sel[NCLS][KSEL];     // selected pixel indices per class
__device__ float g_acc;                 // reset by last ticket each launch
__device__ unsigned int g_tick;
__device__ unsigned int g_selflag;      // classes whose selection is published (0..4)
__device__ unsigned int g_gtick;        // gather-completion ticket (resets flags)

// ================= kernel 1: selection (blocks 0-3) + distributed gather (all 32) — R14 verbatim =================
__global__ __launch_bounds__(1024, 1) void k_select(const float* __restrict__ neg,
                                                    const float* __restrict__ nl) {
    __shared__ int   hist[NBIN];
    __shared__ int   schunk[32];
    __shared__ float cv[MAXCAND];
    __shared__ int   ci[MAXCAND];
    __shared__ int   ssel[KSEL];
    __shared__ int   s_cnt;
    __shared__ int   s_binThr;

    int blk = blockIdx.x;
    int t   = threadIdx.x;

    // ---------- selection: blocks 0..3 only ----------
    if (blk < NCLS) {
        int s = blk;

        int  seg[8];
        float pv[8];
        int  bin[8];
        #pragma unroll
        for (int j = 0; j < 8; j++) {
            int i = t + j * 1024;
            int b = i >> 12, rem = i & 4095;
            const float* pn = nl + (size_t)b * NCLS * HW + rem;
            float l0 = pn[0], l1 = pn[HW], l2 = pn[2 * HW], l3 = pn[3 * HW];
            int amax = 0; float m = l0;
            if (l1 > m) { m = l1; amax = 1; }
            if (l2 > m) { m = l2; amax = 2; }
            if (l3 > m) { m = l3; amax = 3; }
            float sum = __expf(l0 - m) + __expf(l1 - m) + __expf(l2 - m) + __expf(l3 - m);
            seg[j] = amax;
            pv[j]  = 1.0f / sum;
            int bb = (int)((pv[j] - 0.25f) * (1024.0f / 0.75f));
            bin[j] = max(0, min(NBIN - 1, bb));
        }

        for (int i = t; i < NBIN; i += 1024) hist[i] = 0;
        if (t == 0) s_cnt = 0;
        __syncthreads();

        #pragma unroll
        for (int j = 0; j < 8; j++)
            if (seg[j] != s) atomicAdd(&hist[bin[j]], 1);
        __syncthreads();

        if (t < 32) {
            int sum = 0;
            #pragma unroll
            for (int j = 0; j < 32; j++) sum += hist[t * 32 + j];
            schunk[t] = sum;
        }
        __syncthreads();
        if (t == 0) {
            int cum = 0, binThr = 0;
            for (int cb = 31; cb >= 0; cb--) {
                if (cum + schunk[cb] >= KSEL) {
                    for (int bb = cb * 32 + 31; bb >= cb * 32; bb--) {
                        cum += hist[bb];
                        if (cum >= KSEL) { binThr = bb; break; }
                    }
                    break;
                }
                cum += schunk[cb];
            }
            s_binThr = binThr;
        }
        __syncthreads();
        int binThr = s_binThr;

        #pragma unroll
        for (int j = 0; j < 8; j++) {
            if (seg[j] != s && bin[j] >= binThr) {
                int pos = atomicAdd(&s_cnt, 1);
                if (pos < MAXCAND) { cv[pos] = pv[j]; ci[pos] = t + j * 1024; }
            }
        }
        __syncthreads();
        int M = min(s_cnt, MAXCAND);

        // exact rank (value desc, index asc tie-break == lax.top_k)
        for (int c = t; c < M; c += 1024) {
            float v = cv[c]; int id = ci[c];
            int r = 0;
            for (int m = 0; m < M; m++) {
                float vm = cv[m];
                if (vm > v || (vm == v && ci[m] < id)) r++;
            }
            if (r < KSEL) ssel[r] = id;
        }
        __syncthreads();

        if (t < KSEL) g_sel[s][t] = ssel[t];
        __syncthreads();
        if (t == 0) {
            __threadfence();
            atomicAdd(&g_selflag, 1u);
        }
    }

    // ---------- all 32 blocks: wait for all 4 classes published ----------
    if (t == 0) {
        while (atomicAdd(&g_selflag, 0u) < NCLS) __nanosleep(64);
    }
    __syncthreads();

    // ---------- distributed gather: one (class,k) row per warp ----------
    {
        int w = t >> 5, lane = t & 31;
        int T = blk + SELBLK * w;                 // task id 0..199 spread across blocks
        if (T < NCLS * KSEL) {
            int cls = T / KSEL, k = T - cls * KSEL;
            int n = g_sel[cls][k];
            int b = n >> 12, rem = n & 4095;
            const float* p = neg + (size_t)b * CC * HW + rem;
            float v[4];
            #pragma unroll
            for (int j = 0; j < 4; j++)
                v[j] = p[(size_t)(lane + j * 32) * HW];
            float ss = v[0]*v[0] + v[1]*v[1] + v[2]*v[2] + v[3]*v[3];
            #pragma unroll
            for (int off = 16; off; off >>= 1)
                ss += __shfl_xor_sync(0xffffffffu, ss, off);
            float inv = SCALE / fmaxf(sqrtf(ss), 1e-12f);
            #pragma unroll
            for (int j = 0; j < 4; j++)
                g_Gs[cls][k][lane + j * 32] = v[j] * inv;
        }
    }

    // ---------- reset flags for next graph replay ----------
    __syncthreads();
    if (t == 0) {
        __threadfence();
        unsigned int old = atomicAdd(&g_gtick, 1u);
        if (old == SELBLK - 1) {
            g_selflag = 0u;
            g_gtick   = 0u;
        }
    }
}

// ================= kernel 2: fused norm + class-sorted block GEMM (5x10 k-tiling) =================
__global__ __launch_bounds__(NTHR, 1) void k_fused(const float* __restrict__ inp,
                                                   const float* __restrict__ pos,
                                                   const float* __restrict__ il,
                                                   float* __restrict__ out) {
    extern __shared__ float sm[];
    float* sX    = sm + OFF_X;
    float* sP    = sm + OFF_P;
    float* sG    = sm + OFF_G;
    float* sRed  = sm + OFF_RED;
    float* sEx   = sm + OFF_EX;
    float* sInv  = sm + OFF_INV;
    float* sInvP = sm + OFF_INVP;
    float* sNom  = sm + OFF_NOM;
    int*   sCls  = (int*)(sm + OFF_CLS);
    int*   sPerm = (int*)(sm + OFF_PERM);
    int*   sSlot = (int*)(sm + OFF_SLOT);
    int*   sCnt  = (int*)(sm + OFF_CNT);

    int tid = threadIdx.x;
    int n   = tid & 63;
    int cg  = tid >> 6;                  // 0..7 channel group
    int px0 = blockIdx.x * 64;
    int b   = px0 >> 12, rem = px0 & 4095;

    if (tid < 8) sCnt[tid] = 0;

    // ---- G prefetch via cp.async: overlaps phase A ----
    {
        const float4* gsrc = (const float4*)g_Gs;     // 4*56*128/4 = 7168 float4
        #pragma unroll
        for (int it = 0; it < 14; it++) {
            int f4 = tid + it * NTHR;
            int cls = f4 / 1792;
            int r4  = f4 - cls * 1792;
            unsigned dst = (unsigned)__cvta_generic_to_shared(&sG[cls * CS + r4 * 4]);
            asm volatile("cp.async.cg.shared.global [%0], [%1], 16;\n"
                         :: "r"(dst), "l"(gsrc + f4));
        }
        asm volatile("cp.async.commit_group;\n");
    }

    // ---- Phase A: load x/p to registers, partial norms; tid<64: class from input_logits ----
    float xv[16], pv[16];
    {
        const float* bx = inp + (size_t)b * CC * HW + rem + n;
        const float* bp = pos + (size_t)b * CC * HW + rem + n;
        float sx2 = 0.f, sp2 = 0.f, sxp = 0.f;
        #pragma unroll
        for (int j = 0; j < 16; j++) {
            int c = cg * 16 + j;
            xv[j] = bx[(size_t)c * HW];
            pv[j] = bp[(size_t)c * HW];
            sx2 += xv[j] * xv[j];
            sp2 += pv[j] * pv[j];
            sxp += xv[j] * pv[j];
        }
        sRed[(0 * 8 + cg) * 64 + n] = sx2;
        sRed[(1 * 8 + cg) * 64 + n] = sp2;
        sRed[(2 * 8 + cg) * 64 + n] = sxp;
    }
    if (tid < 64) {
        const float* pi = il + (size_t)b * NCLS * HW + rem + tid;
        float l0 = pi[0], l1 = pi[HW], l2 = pi[2 * HW], l3 = pi[3 * HW];
        int amax = 0; float m = l0;
        if (l1 > m) { m = l1; amax = 1; }
        if (l2 > m) { m = l2; amax = 2; }
        if (l3 > m) { m = l3; amax = 3; }
        sCls[tid] = amax;
    }
    __syncthreads();

    if (tid < 64) {
        float a0 = 0.f, a1 = 0.f, a2 = 0.f;
        #pragma unroll
        for (int g = 0; g < 8; g++) {
            a0 += sRed[(0 * 8 + g) * 64 + tid];
            a1 += sRed[(1 * 8 + g) * 64 + tid];
            a2 += sRed[(2 * 8 + g) * 64 + tid];
        }
        float invi = 1.0f / fmaxf(sqrtf(a0), 1e-12f);
        float invp = 1.0f / fmaxf(sqrtf(a1), 1e-12f);
        sInv[tid]  = invi;
        sInvP[tid] = invp;
        sNom[tid]  = exp2f(a2 * invi * invp * SCALE);
        atomicAdd(&sCnt[sCls[tid]], 1);
    }
    __syncthreads();
    if (tid == 0) {
        int acc = 0;
        #pragma unroll
        for (int c = 0; c < 4; c++) { sCnt[4 + c] = acc; acc += sCnt[c]; }
    }
    __syncthreads();
    if (tid < 64) {
        int pos2 = atomicAdd(&sCnt[4 + sCls[tid]], 1);
        sPerm[pos2] = tid;
        sSlot[tid]  = pos2;
    }
    __syncthreads();

    // store normalized x̂/p̂ at class-sorted rows
    {
        float invi = sInv[n], invp = sInvP[n];
        int slot = sSlot[n];
        float* dx = sX + slot * RS + cg * 16;
        float* dp = sP + slot * RS + cg * 16;
        #pragma unroll
        for (int j4 = 0; j4 < 4; j4++) {
            *(float4*)&dx[j4 * 4] = make_float4(xv[j4*4]*invi, xv[j4*4+1]*invi,
                                                xv[j4*4+2]*invi, xv[j4*4+3]*invi);
            *(float4*)&dp[j4 * 4] = make_float4(pv[j4*4]*invp, pv[j4*4+1]*invp,
                                                pv[j4*4+2]*invp, pv[j4*4+3]*invp);
        }
    }

    // G must have landed; make all smem writes visible
    asm volatile("cp.async.wait_group 0;\n" ::: "memory");
    __syncthreads();

    // ---- Phase C: register-tiled GEMM, 10 warps: 2 halves x 5 kg, 10 k each (5*10 = 50 exact) ----
    {
        int lane = tid & 31, w = tid >> 5;           // warps 0..15; 0..9 active
        if (w < 10) {
            int half = w & 1, kg = w >> 1;           // kg 0..4
            int slot = half * 32 + lane;
            int cls  = sCls[sPerm[slot]];
            const float* gx = sX + slot * RS;
            const float* gp = sP + slot * RS;
            const float* gg = sG + cls * CS + (kg * 10) * CC;

            u64 aN[10], aA[10];
            #pragma unroll
            for (int kk = 0; kk < 10; kk++) { aN[kk] = 0ull; aA[kk] = 0ull; }

            #pragma unroll 2
            for (int c4 = 0; c4 < 32; c4++) {
                ulonglong2 x2 = *(const ulonglong2*)&gx[c4 * 4];
                ulonglong2 p2 = *(const ulonglong2*)&gp[c4 * 4];
                #pragma unroll
                for (int kk = 0; kk < 10; kk++) {
                    ulonglong2 g2 = *(const ulonglong2*)&gg[kk * CC + c4 * 4];
                    fma2(aN[kk], x2.x, g2.x); fma2(aN[kk], x2.y, g2.y);
                    fma2(aA[kk], p2.x, g2.x); fma2(aA[kk], p2.y, g2.y);
                }
            }

            float eN = 0.f, eA = 0.f;
            #pragma unroll
            for (int kk = 0; kk < 10; kk++) {
                float2 tn = upk(aN[kk]);
                float2 ta = upk(aA[kk]);
                eN += exp2f(tn.x + tn.y);
                eA += exp2f(ta.x + ta.y);
            }
            sEx[kg * 64 + slot]       = eN;
            sEx[(5 + kg) * 64 + slot] = eA;
        }
    }
    __syncthreads();

    // ---- epilogue + ticketed output ----
    if (tid < 64) {
        float accN = 0.f, accA = 0.f;
        #pragma unroll
        for (int g = 0; g < 5; g++) {
            accN += sEx[g * 64 + tid];
            accA += sEx[(5 + g) * 64 + tid];
        }
        float nom = sNom[sPerm[tid]];
        float term = logf(nom / (accN + nom + 1e-8f))
                   + logf(nom / (accA + nom + 1e-8f));
        #pragma unroll
        for (int off = 16; off; off >>= 1)
            term += __shfl_xor_sync(0xffffffffu, term, off);
        if ((tid & 31) == 0) atomicAdd(&g_acc, term);
    }
    __syncthreads();

    if (tid == 0) {
        __threadfence();
        unsigned int ticket = atomicAdd(&g_tick, 1u);
        if (ticket == gridDim.x - 1) {
            float v = atomicAdd(&g_acc, 0.0f);
            out[0] = -v / (float)NPIX;
            g_tick = 0u;
            g_acc  = 0.0f;              // reset for next graph replay
        }
    }
}

// ---------------- launch ----------------
extern "C" void kernel_launch(void* const* d_in, const int* in_sizes, int n_in,
                              void* d_out, int out_size) {
    const float* inp = (const float*)d_in[0];   // input    [2,128,64,64]
    const float* pos = (const float*)d_in[1];   // positive
    const float* neg = (const float*)d_in[2];   // negative
    const float* il  = (const float*)d_in[3];   // input_logits    [2,4,64,64]
    const float* nl  = (const float*)d_in[4];   // negative_logits
    float* out = (float*)d_out;

    cudaFuncSetAttribute(k_fused, cudaFuncAttributeMaxDynamicSharedMemorySize, SMEM_BYTES);

    k_select<<<SELBLK, 1024>>>(neg, nl);
    k_fused<<<NPIX / 64, NTHR, SMEM_BYTES>>>(inp, pos, il, out);
}